// round 1
// baseline (speedup 1.0000x reference)
#include <cuda_runtime.h>
#include <math.h>

// Problem constants
#define BB 128
#define NN 100
#define DD 2048
#define HH 1024
#define OO 1600
#define AAd 400
#define LL 2048
#define MM (BB*NN)   // 12800

// ---------------- device scratch (no allocs allowed) ----------------
__device__ float g_h1[(size_t)MM * HH];      // 52.4 MB
__device__ float g_h2[(size_t)MM * HH];      // 52.4 MB
__device__ float g_lo[(size_t)MM * OO];      // 81.9 MB (obj logits)
__device__ float g_la[(size_t)MM * AAd];     // 20.5 MB (att logits)
__device__ float2 g_st_o[MM];                // (rowmax, sumexp)
__device__ float2 g_st_a[MM];
__device__ int   g_rowmap[MM];               // compact row -> b*NN+n
__device__ int   g_rowstart[BB];
__device__ int   g_Meff;
__device__ int   g_desc[LL];

// ---------------- f32x2 packed FMA helpers (sm_103a) ----------------
__device__ __forceinline__ void ffma2(unsigned long long &acc,
                                      unsigned long long a,
                                      unsigned long long b) {
    asm("fma.rn.f32x2 %0, %1, %2, %0;" : "+l"(acc) : "l"(a), "l"(b));
}
__device__ __forceinline__ unsigned long long pack2(float x, float y) {
    unsigned long long r;
    asm("mov.b64 %0, {%1, %2};" : "=l"(r) : "f"(x), "f"(y));
    return r;
}
__device__ __forceinline__ float2 unpack2(unsigned long long v) {
    float2 r;
    asm("mov.b64 {%0, %1}, %2;" : "=f"(r.x), "=f"(r.y) : "l"(v));
    return r;
}

// ---------------- setup: live-row compaction ----------------
__global__ void setup_kernel(const int* __restrict__ num_descs) {
    __shared__ int cnt[BB];
    int b = threadIdx.x;  // 128 threads
    int c = num_descs[b];
    if (c < 1) c = 1;
    cnt[b] = c;
    __syncthreads();
    if (b == 0) {
        int acc = 0;
        for (int i = 0; i < BB; i++) { g_rowstart[i] = acc; acc += cnt[i]; }
        g_Meff = acc;
    }
    __syncthreads();
    int start = g_rowstart[b];
    for (int i = 0; i < c; i++) g_rowmap[start + i] = b * NN + i;
}

// ---------------- SGEMM: C[M,N] = act(A[M,K] @ W[K,N] + bias) ----------------
// 128x128 tile, BK=16, 256 threads, 8x8 per thread, f32x2 accumulators.
// GATHER: A rows are indirected through g_rowmap (for reading x).
template<bool RELU, bool GATHER>
__global__ __launch_bounds__(256, 2)
void sgemm_kernel(const float* __restrict__ A, const float* __restrict__ Bw,
                  const float* __restrict__ bias, float* __restrict__ C,
                  int N, int K)
{
    const int Meff = g_Meff;
    const int rowBase = blockIdx.y * 128;
    if (rowBase >= Meff) return;
    const int colBase = blockIdx.x * 128;
    const int tid = threadIdx.x;

    __shared__ float As[16][132];   // transposed A tile, padded (2-way store conflict max)
    __shared__ float Bs[16][128];
    __shared__ int   rmap[128];

    if (tid < 128) {
        int rr = rowBase + tid;
        if (GATHER) rmap[tid] = g_rowmap[rr < Meff ? rr : 0];
        else        rmap[tid] = rr;   // compact buffer, always < MM
    }
    __syncthreads();

    // A-load mapping: 512 float4/tile, 2 per thread
    const int aRow0 = tid >> 2;
    const int aRow1 = aRow0 + 64;
    const int aCol  = (tid & 3) << 2;
    const float* Ap0 = A + (size_t)rmap[aRow0] * K + aCol;
    const float* Ap1 = A + (size_t)rmap[aRow1] * K + aCol;

    // B-load mapping: 512 float4/tile, 2 per thread
    const int bRow0 = tid >> 5;
    const int bRow1 = bRow0 + 8;
    const int bCol  = (tid & 31) << 2;
    const int gcol  = colBase + bCol;
    const bool bok  = (gcol < N);       // N % 4 == 0, whole-float4 guard
    const float* Bp0 = Bw + (size_t)bRow0 * N + gcol;
    const float* Bp1 = Bw + (size_t)bRow1 * N + gcol;

    unsigned long long acc[8][4];
    #pragma unroll
    for (int i = 0; i < 8; i++)
        #pragma unroll
        for (int j = 0; j < 4; j++) acc[i][j] = 0ull;

    const int tx = tid & 15;
    const int ty = tid >> 4;

    for (int k0 = 0; k0 < K; k0 += 16) {
        float4 a0 = *(const float4*)(Ap0 + k0);
        float4 a1 = *(const float4*)(Ap1 + k0);
        float4 b0 = bok ? *(const float4*)(Bp0 + (size_t)k0 * N) : make_float4(0,0,0,0);
        float4 b1 = bok ? *(const float4*)(Bp1 + (size_t)k0 * N) : make_float4(0,0,0,0);

        As[aCol+0][aRow0] = a0.x; As[aCol+1][aRow0] = a0.y;
        As[aCol+2][aRow0] = a0.z; As[aCol+3][aRow0] = a0.w;
        As[aCol+0][aRow1] = a1.x; As[aCol+1][aRow1] = a1.y;
        As[aCol+2][aRow1] = a1.z; As[aCol+3][aRow1] = a1.w;
        *(float4*)&Bs[bRow0][bCol] = b0;
        *(float4*)&Bs[bRow1][bCol] = b1;
        __syncthreads();

        #pragma unroll
        for (int kk = 0; kk < 16; kk++) {
            float4 ra0 = *(const float4*)&As[kk][ty * 8];
            float4 ra1 = *(const float4*)&As[kk][ty * 8 + 4];
            ulonglong2 rb0 = *(const ulonglong2*)&Bs[kk][tx * 8];
            ulonglong2 rb1 = *(const ulonglong2*)&Bs[kk][tx * 8 + 4];
            float av[8] = {ra0.x, ra0.y, ra0.z, ra0.w, ra1.x, ra1.y, ra1.z, ra1.w};
            #pragma unroll
            for (int i = 0; i < 8; i++) {
                unsigned long long a2 = pack2(av[i], av[i]);
                ffma2(acc[i][0], a2, rb0.x);
                ffma2(acc[i][1], a2, rb0.y);
                ffma2(acc[i][2], a2, rb1.x);
                ffma2(acc[i][3], a2, rb1.y);
            }
        }
        __syncthreads();
    }

    // epilogue: bias (+relu), guarded stores
    #pragma unroll
    for (int i = 0; i < 8; i++) {
        int row = rowBase + ty * 8 + i;
        if (row >= Meff) break;
        #pragma unroll
        for (int jp = 0; jp < 2; jp++) {
            int col = colBase + tx * 8 + jp * 4;
            if (col < N) {
                float4 bv = *(const float4*)(bias + col);
                float2 p0 = unpack2(acc[i][jp * 2 + 0]);
                float2 p1 = unpack2(acc[i][jp * 2 + 1]);
                float4 v;
                v.x = p0.x + bv.x; v.y = p0.y + bv.y;
                v.z = p1.x + bv.z; v.w = p1.y + bv.w;
                if (RELU) {
                    v.x = fmaxf(v.x, 0.f); v.y = fmaxf(v.y, 0.f);
                    v.z = fmaxf(v.z, 0.f); v.w = fmaxf(v.w, 0.f);
                }
                *(float4*)(C + (size_t)row * N + col) = v;
            }
        }
    }
}

// ---------------- per-row softmax stats: (max, sum exp) ----------------
__global__ void rowstats_kernel(const float* __restrict__ logits,
                                float2* __restrict__ stats, int ncols)
{
    int r = blockIdx.x;
    if (r >= g_Meff) return;
    const float* p = logits + (size_t)r * ncols;
    const int tid = threadIdx.x;   // 128
    __shared__ float red[128];

    float mx = -3.402823466e38f;
    for (int j = tid; j < ncols; j += 128) mx = fmaxf(mx, p[j]);
    red[tid] = mx; __syncthreads();
    for (int s = 64; s; s >>= 1) {
        if (tid < s) red[tid] = fmaxf(red[tid], red[tid + s]);
        __syncthreads();
    }
    mx = red[0]; __syncthreads();

    float sum = 0.f;
    for (int j = tid; j < ncols; j += 128) sum += expf(p[j] - mx);
    red[tid] = sum; __syncthreads();
    for (int s = 64; s; s >>= 1) {
        if (tid < s) red[tid] += red[tid + s];
        __syncthreads();
    }
    if (tid == 0) stats[r] = make_float2(mx, red[0]);
}

// ---------------- score + argmax: one warp per label row ----------------
__global__ void score_kernel(const int* __restrict__ label_img,
                             const int* __restrict__ obj_labels,
                             const int* __restrict__ att_labels,
                             const int* __restrict__ num_descs)
{
    int l = blockIdx.x * 8 + (threadIdx.x >> 5);
    int lane = threadIdx.x & 31;
    if (l >= LL) return;
    int b  = label_img[l];
    int nd = num_descs[b];
    int oj = obj_labels[l];
    int aj = att_labels[l];
    int rs = g_rowstart[b];

    float best = -1.0f;   // all valid scores are >= 0
    int   bidx = 0;
    for (int n = lane; n < nd; n += 32) {
        int r = rs + n;
        float2 so = g_st_o[r];
        float2 sa = g_st_a[r];
        float po = expf(g_lo[(size_t)r * OO  + oj] - so.x) / so.y;
        float pa = expf(g_la[(size_t)r * AAd + aj] - sa.x) / sa.y;
        float s = po * pa;
        if (s > best) { best = s; bidx = n; }
    }
    #pragma unroll
    for (int off = 16; off; off >>= 1) {
        float ob = __shfl_down_sync(0xffffffffu, best, off);
        int   oi = __shfl_down_sync(0xffffffffu, bidx, off);
        if (ob > best || (ob == best && oi < bidx)) { best = ob; bidx = oi; }
    }
    if (lane == 0) g_desc[l] = bidx;
}

// ---------------- final gather: softmax of the selected row ----------------
__global__ void gather_kernel(const int* __restrict__ label_img,
                              float* __restrict__ out)
{
    int l = blockIdx.x;
    int b = label_img[l];
    int r = g_rowstart[b] + g_desc[l];

    float2 so = g_st_o[r];
    float inv_o = 1.0f / so.y;
    const float* lo = g_lo + (size_t)r * OO;
    float* oo = out + (size_t)l * OO;
    for (int j = threadIdx.x; j < OO; j += blockDim.x)
        oo[j] = expf(lo[j] - so.x) * inv_o;

    float2 sa = g_st_a[r];
    float inv_a = 1.0f / sa.y;
    const float* la = g_la + (size_t)r * AAd;
    float* oa = out + (size_t)LL * OO + (size_t)l * AAd;
    for (int j = threadIdx.x; j < AAd; j += blockDim.x)
        oa[j] = expf(la[j] - sa.x) * inv_a;
}

// ---------------- launch ----------------
extern "C" void kernel_launch(void* const* d_in, const int* in_sizes, int n_in,
                              void* d_out, int out_size)
{
    const float* x          = (const float*)d_in[0];
    const int*   num_descs  = (const int*)  d_in[1];
    const int*   label_img  = (const int*)  d_in[2];
    const int*   obj_labels = (const int*)  d_in[3];
    const int*   att_labels = (const int*)  d_in[4];
    const float* w1o = (const float*)d_in[5];
    const float* b1o = (const float*)d_in[6];
    const float* w2o = (const float*)d_in[7];
    const float* b2o = (const float*)d_in[8];
    const float* w3o = (const float*)d_in[9];
    const float* b3o = (const float*)d_in[10];
    const float* w1a = (const float*)d_in[11];
    const float* b1a = (const float*)d_in[12];
    const float* w2a = (const float*)d_in[13];
    const float* b2a = (const float*)d_in[14];
    const float* w3a = (const float*)d_in[15];
    const float* b3a = (const float*)d_in[16];
    float* out = (float*)d_out;

    float *h1, *h2, *lo, *la;
    float2 *sto, *sta;
    cudaGetSymbolAddress((void**)&h1,  g_h1);
    cudaGetSymbolAddress((void**)&h2,  g_h2);
    cudaGetSymbolAddress((void**)&lo,  g_lo);
    cudaGetSymbolAddress((void**)&la,  g_la);
    cudaGetSymbolAddress((void**)&sto, g_st_o);
    cudaGetSymbolAddress((void**)&sta, g_st_a);

    const int MT = 100;  // ceil(12800/128) M tiles (blocks past g_Meff exit)

    setup_kernel<<<1, BB>>>(num_descs);

    // object branch
    sgemm_kernel<true,  true ><<<dim3(HH/128, MT), 256>>>(x,  w1o, b1o, h1, HH, DD);
    sgemm_kernel<true,  false><<<dim3(HH/128, MT), 256>>>(h1, w2o, b2o, h2, HH, HH);
    sgemm_kernel<false, false><<<dim3((OO+127)/128, MT), 256>>>(h2, w3o, b3o, lo, OO, HH);
    rowstats_kernel<<<MM, 128>>>(lo, sto, OO);

    // attribute branch (reuses h1/h2)
    sgemm_kernel<true,  true ><<<dim3(HH/128, MT), 256>>>(x,  w1a, b1a, h1, HH, DD);
    sgemm_kernel<true,  false><<<dim3(HH/128, MT), 256>>>(h1, w2a, b2a, h2, HH, HH);
    sgemm_kernel<false, false><<<dim3((AAd+127)/128, MT), 256>>>(h2, w3a, b3a, la, AAd, HH);
    rowstats_kernel<<<MM, 128>>>(la, sta, AAd);

    score_kernel<<<(LL + 7) / 8, 256>>>(label_img, obj_labels, att_labels, num_descs);
    gather_kernel<<<LL, 256>>>(label_img, out);
}

// round 3
// speedup vs baseline: 2.8252x; 2.8252x over previous
#include <cuda_runtime.h>
#include <cuda_bf16.h>
#include <math.h>
#include <stdint.h>

// Problem constants
#define BB 128
#define NN 100
#define DD 2048
#define HH 1024
#define OO 1600
#define AAd 400
#define LL 2048
#define MM (BB*NN)   // 12800

#define OPAD 1664    // OO padded to 128
#define APAD 512     // AAd padded to 128

// ---------------- device scratch (no allocs allowed) ----------------
__device__ __nv_bfloat16 g_xc_hi[(size_t)MM * DD];
__device__ __nv_bfloat16 g_xc_lo[(size_t)MM * DD];
__device__ __nv_bfloat16 g_h1_hi[(size_t)MM * HH];
__device__ __nv_bfloat16 g_h1_lo[(size_t)MM * HH];
__device__ __nv_bfloat16 g_h2_hi[(size_t)MM * HH];
__device__ __nv_bfloat16 g_h2_lo[(size_t)MM * HH];
__device__ __nv_bfloat16 g_wt1o_hi[(size_t)HH * DD];
__device__ __nv_bfloat16 g_wt1o_lo[(size_t)HH * DD];
__device__ __nv_bfloat16 g_wt2o_hi[(size_t)HH * HH];
__device__ __nv_bfloat16 g_wt2o_lo[(size_t)HH * HH];
__device__ __nv_bfloat16 g_wt3o_hi[(size_t)OPAD * HH];
__device__ __nv_bfloat16 g_wt3o_lo[(size_t)OPAD * HH];
__device__ __nv_bfloat16 g_wt1a_hi[(size_t)HH * DD];
__device__ __nv_bfloat16 g_wt1a_lo[(size_t)HH * DD];
__device__ __nv_bfloat16 g_wt2a_hi[(size_t)HH * HH];
__device__ __nv_bfloat16 g_wt2a_lo[(size_t)HH * HH];
__device__ __nv_bfloat16 g_wt3a_hi[(size_t)APAD * HH];
__device__ __nv_bfloat16 g_wt3a_lo[(size_t)APAD * HH];
__device__ float g_lo[(size_t)MM * OO];
__device__ float g_la[(size_t)MM * AAd];
__device__ float2 g_st_o[MM];
__device__ float2 g_st_a[MM];
__device__ int   g_rowmap[MM];
__device__ int   g_rowstart[BB];
__device__ int   g_Meff;
__device__ int   g_desc[LL];

// ---------------- PTX helpers (baseline sm_80+ features only) ----------------
__device__ __forceinline__ uint32_t smem_u32_of(const void* p) {
    uint32_t a;
    asm("{ .reg .u64 t; cvta.to.shared.u64 t, %1; cvt.u32.u64 %0, t; }" : "=r"(a) : "l"(p));
    return a;
}
__device__ __forceinline__ void cp16(uint32_t dst, const void* src) {
    asm volatile("cp.async.cg.shared.global [%0], [%1], 16;" :: "r"(dst), "l"(src) : "memory");
}
__device__ __forceinline__ void cp_commit() {
    asm volatile("cp.async.commit_group;" ::: "memory");
}
template<int N>
__device__ __forceinline__ void cp_wait() {
    asm volatile("cp.async.wait_group %0;" :: "n"(N) : "memory");
}
__device__ __forceinline__ void ldsm4(uint32_t* r, uint32_t addr) {
    asm volatile("ldmatrix.sync.aligned.m8n8.x4.shared.b16 {%0,%1,%2,%3}, [%4];"
        : "=r"(r[0]), "=r"(r[1]), "=r"(r[2]), "=r"(r[3]) : "r"(addr));
}
__device__ __forceinline__ void mma16816(float* c, const uint32_t* a, const uint32_t* b) {
    asm volatile("mma.sync.aligned.m16n8k16.row.col.f32.bf16.bf16.f32 "
        "{%0,%1,%2,%3}, {%4,%5,%6,%7}, {%8,%9}, {%0,%1,%2,%3};"
        : "+f"(c[0]), "+f"(c[1]), "+f"(c[2]), "+f"(c[3])
        : "r"(a[0]), "r"(a[1]), "r"(a[2]), "r"(a[3]), "r"(b[0]), "r"(b[1]));
}

// ---------------- setup: live-row compaction ----------------
__global__ void setup_kernel(const int* __restrict__ num_descs) {
    __shared__ int cnt[BB];
    int b = threadIdx.x;
    int c = num_descs[b];
    if (c < 1) c = 1;
    cnt[b] = c;
    __syncthreads();
    if (b == 0) {
        int acc = 0;
        for (int i = 0; i < BB; i++) { g_rowstart[i] = acc; acc += cnt[i]; }
        g_Meff = acc;
    }
    __syncthreads();
    int start = g_rowstart[b];
    for (int i = 0; i < c; i++) g_rowmap[start + i] = b * NN + i;
}

// ---------------- x compaction + bf16 hi/lo split ----------------
__global__ void xsplit_kernel(const float* __restrict__ x) {
    int r = blockIdx.x;
    int Meff = g_Meff;
    int mceil = (Meff + 127) & ~127;
    if (r >= mceil) return;
    int src = g_rowmap[r < Meff ? r : (Meff - 1)];
    const float4* xp = (const float4*)(x + (size_t)src * DD);
    uint32_t* dh = (uint32_t*)(g_xc_hi + (size_t)r * DD);
    uint32_t* dl = (uint32_t*)(g_xc_lo + (size_t)r * DD);
    for (int i = threadIdx.x; i < DD / 4; i += 256) {
        float4 v = xp[i];
        __nv_bfloat16 h0 = __float2bfloat16(v.x);
        __nv_bfloat16 h1 = __float2bfloat16(v.y);
        __nv_bfloat16 h2 = __float2bfloat16(v.z);
        __nv_bfloat16 h3 = __float2bfloat16(v.w);
        __nv_bfloat16 l0 = __float2bfloat16(v.x - __bfloat162float(h0));
        __nv_bfloat16 l1 = __float2bfloat16(v.y - __bfloat162float(h1));
        __nv_bfloat16 l2 = __float2bfloat16(v.z - __bfloat162float(h2));
        __nv_bfloat16 l3 = __float2bfloat16(v.w - __bfloat162float(h3));
        __nv_bfloat162 ph0; ph0.x = h0; ph0.y = h1;
        __nv_bfloat162 ph1; ph1.x = h2; ph1.y = h3;
        __nv_bfloat162 pl0; pl0.x = l0; pl0.y = l1;
        __nv_bfloat162 pl1; pl1.x = l2; pl1.y = l3;
        dh[2*i]   = *(uint32_t*)&ph0;
        dh[2*i+1] = *(uint32_t*)&ph1;
        dl[2*i]   = *(uint32_t*)&pl0;
        dl[2*i+1] = *(uint32_t*)&pl1;
    }
}

// ---------------- weight transpose + split: W[K][N] -> T[Npad][K] hi/lo ----------------
__global__ void wsplit_kernel(const float* __restrict__ W,
                              __nv_bfloat16* __restrict__ Thi,
                              __nv_bfloat16* __restrict__ Tlo,
                              int K, int N) {
    __shared__ float t[32][33];
    int n0 = blockIdx.x * 32, k0 = blockIdx.y * 32;
    int tx = threadIdx.x, ty = threadIdx.y;
    for (int i = ty; i < 32; i += 8) {
        int n = n0 + tx;
        t[i][tx] = (n < N) ? W[(size_t)(k0 + i) * N + n] : 0.f;
    }
    __syncthreads();
    for (int i = ty; i < 32; i += 8) {
        int n = n0 + i;
        if (n < N) {
            float v = t[tx][i];
            __nv_bfloat16 h = __float2bfloat16(v);
            Thi[(size_t)n * K + k0 + tx] = h;
            Tlo[(size_t)n * K + k0 + tx] = __float2bfloat16(v - __bfloat162float(h));
        }
    }
}

// ---------------- HMMA split-bf16 GEMM ----------------
// Tile 128x128, K-chunk 64, cp.async 2-stage, SW128-xor swizzled smem.
// smem per stage: Ahi|Alo|Bhi|Blo 16KB each = 64KB; 2 stages = 128KB.
#define STG_BYTES 65536
#define GEMM_SMEM 131072

// load one 128x64 bf16 tile into swizzled smem via cp.async (256 threads)
__device__ __forceinline__ void load_tile_async(const __nv_bfloat16* __restrict__ g,
                                                int rowStride, int row0, int k0,
                                                uint32_t sbase_tile, int tid) {
    #pragma unroll
    for (int it = 0; it < 4; it++) {
        int v = tid + it * 256;            // 0..1023
        int r = v >> 3, cv = v & 7;        // row, 16B chunk
        const void* src = g + (size_t)(row0 + r) * rowStride + k0 + cv * 8;
        uint32_t cb = (uint32_t)(cv * 16);
        uint32_t sw = (uint32_t)(r * 128) + (cb ^ (((uint32_t)r & 7u) << 4));
        cp16(sbase_tile + sw, src);
    }
}

// swizzled smem address: tile base + row*128 + (chunkbyte ^ ((row&7)<<4))
__device__ __forceinline__ uint32_t swaddr(uint32_t base, int row, int cb) {
    return base + (uint32_t)(row * 128) + (((uint32_t)cb) ^ (((uint32_t)row & 7u) << 4));
}

// OUTMODE 0: relu + bf16 hi/lo outputs.  OUTMODE 1: fp32 outputs, no relu.
template<int OUTMODE>
__global__ __launch_bounds__(256, 1)
void mma_gemm(const __nv_bfloat16* __restrict__ Ahi, const __nv_bfloat16* __restrict__ Alo,
              const __nv_bfloat16* __restrict__ Bhi, const __nv_bfloat16* __restrict__ Blo,
              const float* __restrict__ bias,
              float* __restrict__ Cf,
              __nv_bfloat16* __restrict__ Chi, __nv_bfloat16* __restrict__ Clo,
              int N, int K)
{
    const int Meff = g_Meff;
    const int rowBase = blockIdx.y * 128;
    if (rowBase >= Meff) return;
    const int colBase = blockIdx.x * 128;
    const int tid = threadIdx.x;
    extern __shared__ char smem[];
    const uint32_t sbase = smem_u32_of(smem);

    const int warp = tid >> 5, lane = tid & 31;
    const int wm = (warp >> 2) * 64;     // warp M offset within tile
    const int wn = (warp & 3) * 32;      // warp N offset within tile

    float acc[4][4][4];
    #pragma unroll
    for (int i = 0; i < 4; i++)
        #pragma unroll
        for (int j = 0; j < 4; j++)
            #pragma unroll
            for (int c = 0; c < 4; c++) acc[i][j][c] = 0.f;

    const int nk = K >> 6;

    // prologue: prefetch chunks 0 and 1
    {
        uint32_t st0 = sbase;
        load_tile_async(Ahi, K, rowBase, 0, st0,          tid);
        load_tile_async(Alo, K, rowBase, 0, st0 + 16384,  tid);
        load_tile_async(Bhi, K, colBase, 0, st0 + 32768,  tid);
        load_tile_async(Blo, K, colBase, 0, st0 + 49152,  tid);
        cp_commit();
        uint32_t st1 = sbase + STG_BYTES;
        load_tile_async(Ahi, K, rowBase, 64, st1,          tid);
        load_tile_async(Alo, K, rowBase, 64, st1 + 16384,  tid);
        load_tile_async(Bhi, K, colBase, 64, st1 + 32768,  tid);
        load_tile_async(Blo, K, colBase, 64, st1 + 49152,  tid);
        cp_commit();
    }

    // per-lane ldmatrix row indices
    const int aRowL = wm + (lane & 15);              // + mi*16
    const int aSel  = (lane >> 4);                   // 0/1 -> +8 k-chunk
    const int bRowL = wn + (lane & 7) + ((lane >> 4) << 3);  // + pair*16
    const int bSel  = (lane >> 3) & 1;               // 0/1 -> +8 k-chunk

    for (int i = 0; i < nk; i++) {
        if (i == nk - 1) cp_wait<0>(); else cp_wait<1>();
        __syncthreads();

        const uint32_t sA  = sbase + (uint32_t)(i & 1) * STG_BYTES;
        const uint32_t sAl = sA + 16384;
        const uint32_t sBh = sA + 32768;
        const uint32_t sBl = sA + 49152;

        #pragma unroll
        for (int kk = 0; kk < 4; kk++) {
            const int k0 = kk * 16;
            const int aCb = (k0 >> 3) * 16 + aSel * 16;
            const int bCb = (k0 >> 3) * 16 + bSel * 16;

            uint32_t af[16], bhf[8], blf[8];
            #pragma unroll
            for (int mi = 0; mi < 4; mi++)
                ldsm4(&af[mi * 4], swaddr(sA, aRowL + mi * 16, aCb));
            #pragma unroll
            for (int p = 0; p < 2; p++) {
                ldsm4(&bhf[p * 4], swaddr(sBh, bRowL + p * 16, bCb));
                ldsm4(&blf[p * 4], swaddr(sBl, bRowL + p * 16, bCb));
            }
            // hi*hi and hi*lo
            #pragma unroll
            for (int mi = 0; mi < 4; mi++)
                #pragma unroll
                for (int ni = 0; ni < 4; ni++) {
                    mma16816(acc[mi][ni], &af[mi * 4], &bhf[ni * 2]);
                    mma16816(acc[mi][ni], &af[mi * 4], &blf[ni * 2]);
                }
            // lo*hi
            #pragma unroll
            for (int mi = 0; mi < 4; mi++)
                ldsm4(&af[mi * 4], swaddr(sAl, aRowL + mi * 16, aCb));
            #pragma unroll
            for (int mi = 0; mi < 4; mi++)
                #pragma unroll
                for (int ni = 0; ni < 4; ni++)
                    mma16816(acc[mi][ni], &af[mi * 4], &bhf[ni * 2]);
        }

        if (i + 2 < nk) {
            __syncthreads();   // all warps done reading this stage
            const int k0 = (i + 2) << 6;
            uint32_t st = sbase + (uint32_t)(i & 1) * STG_BYTES;
            load_tile_async(Ahi, K, rowBase, k0, st,          tid);
            load_tile_async(Alo, K, rowBase, k0, st + 16384,  tid);
            load_tile_async(Bhi, K, colBase, k0, st + 32768,  tid);
            load_tile_async(Blo, K, colBase, k0, st + 49152,  tid);
            cp_commit();
        }
    }

    // epilogue from register accumulators
    #pragma unroll
    for (int mi = 0; mi < 4; mi++) {
        #pragma unroll
        for (int ni = 0; ni < 4; ni++) {
            const int col = colBase + wn + ni * 8 + (lane & 3) * 2;
            if (col < N) {
                const float2 bv = *(const float2*)(bias + col);
                #pragma unroll
                for (int h = 0; h < 2; h++) {
                    const int row = rowBase + wm + mi * 16 + (lane >> 2) + h * 8;
                    float v0 = acc[mi][ni][h * 2 + 0] + bv.x;
                    float v1 = acc[mi][ni][h * 2 + 1] + bv.y;
                    if (OUTMODE == 0) {
                        v0 = fmaxf(v0, 0.f);
                        v1 = fmaxf(v1, 0.f);
                        __nv_bfloat16 h0 = __float2bfloat16(v0);
                        __nv_bfloat16 h1 = __float2bfloat16(v1);
                        __nv_bfloat16 l0 = __float2bfloat16(v0 - __bfloat162float(h0));
                        __nv_bfloat16 l1 = __float2bfloat16(v1 - __bfloat162float(h1));
                        __nv_bfloat162 ph; ph.x = h0; ph.y = h1;
                        __nv_bfloat162 pl; pl.x = l0; pl.y = l1;
                        *(uint32_t*)(Chi + (size_t)row * N + col) = *(uint32_t*)&ph;
                        *(uint32_t*)(Clo + (size_t)row * N + col) = *(uint32_t*)&pl;
                    } else {
                        float2 v; v.x = v0; v.y = v1;
                        *(float2*)(Cf + (size_t)row * N + col) = v;
                    }
                }
            }
        }
    }
}

// ---------------- per-row softmax stats: (max, sum exp) ----------------
__global__ void rowstats_kernel(const float* __restrict__ logits,
                                float2* __restrict__ stats, int ncols)
{
    int r = blockIdx.x;
    if (r >= g_Meff) return;
    const float* p = logits + (size_t)r * ncols;
    const int tid = threadIdx.x;   // 128
    __shared__ float red[128];

    float mx = -3.402823466e38f;
    for (int j = tid; j < ncols; j += 128) mx = fmaxf(mx, p[j]);
    red[tid] = mx; __syncthreads();
    for (int s = 64; s; s >>= 1) {
        if (tid < s) red[tid] = fmaxf(red[tid], red[tid + s]);
        __syncthreads();
    }
    mx = red[0]; __syncthreads();

    float sum = 0.f;
    for (int j = tid; j < ncols; j += 128) sum += expf(p[j] - mx);
    red[tid] = sum; __syncthreads();
    for (int s = 64; s; s >>= 1) {
        if (tid < s) red[tid] += red[tid + s];
        __syncthreads();
    }
    if (tid == 0) stats[r] = make_float2(mx, red[0]);
}

// ---------------- score + argmax: one warp per label row ----------------
__global__ void score_kernel(const int* __restrict__ label_img,
                             const int* __restrict__ obj_labels,
                             const int* __restrict__ att_labels,
                             const int* __restrict__ num_descs)
{
    int l = blockIdx.x * 8 + (threadIdx.x >> 5);
    int lane = threadIdx.x & 31;
    if (l >= LL) return;
    int b  = label_img[l];
    int nd = num_descs[b];
    int oj = obj_labels[l];
    int aj = att_labels[l];
    int rs = g_rowstart[b];

    float best = -1.0f;
    int   bidx = 0;
    for (int n = lane; n < nd; n += 32) {
        int r = rs + n;
        float2 so = g_st_o[r];
        float2 sa = g_st_a[r];
        float po = expf(g_lo[(size_t)r * OO  + oj] - so.x) / so.y;
        float pa = expf(g_la[(size_t)r * AAd + aj] - sa.x) / sa.y;
        float s = po * pa;
        if (s > best) { best = s; bidx = n; }
    }
    #pragma unroll
    for (int off = 16; off; off >>= 1) {
        float ob = __shfl_down_sync(0xffffffffu, best, off);
        int   oi = __shfl_down_sync(0xffffffffu, bidx, off);
        if (ob > best || (ob == best && oi < bidx)) { best = ob; bidx = oi; }
    }
    if (lane == 0) g_desc[l] = bidx;
}

// ---------------- final gather: softmax of the selected row ----------------
__global__ void gather_kernel(const int* __restrict__ label_img,
                              float* __restrict__ out)
{
    int l = blockIdx.x;
    int b = label_img[l];
    int r = g_rowstart[b] + g_desc[l];

    float2 so = g_st_o[r];
    float inv_o = 1.0f / so.y;
    const float* lo = g_lo + (size_t)r * OO;
    float* oo = out + (size_t)l * OO;
    for (int j = threadIdx.x; j < OO; j += blockDim.x)
        oo[j] = expf(lo[j] - so.x) * inv_o;

    float2 sa = g_st_a[r];
    float inv_a = 1.0f / sa.y;
    const float* la = g_la + (size_t)r * AAd;
    float* oa = out + (size_t)LL * OO + (size_t)l * AAd;
    for (int j = threadIdx.x; j < AAd; j += blockDim.x)
        oa[j] = expf(la[j] - sa.x) * inv_a;
}

// ---------------- launch ----------------
extern "C" void kernel_launch(void* const* d_in, const int* in_sizes, int n_in,
                              void* d_out, int out_size)
{
    const float* x          = (const float*)d_in[0];
    const int*   num_descs  = (const int*)  d_in[1];
    const int*   label_img  = (const int*)  d_in[2];
    const int*   obj_labels = (const int*)  d_in[3];
    const int*   att_labels = (const int*)  d_in[4];
    const float* w1o = (const float*)d_in[5];
    const float* b1o = (const float*)d_in[6];
    const float* w2o = (const float*)d_in[7];
    const float* b2o = (const float*)d_in[8];
    const float* w3o = (const float*)d_in[9];
    const float* b3o = (const float*)d_in[10];
    const float* w1a = (const float*)d_in[11];
    const float* b1a = (const float*)d_in[12];
    const float* w2a = (const float*)d_in[13];
    const float* b2a = (const float*)d_in[14];
    const float* w3a = (const float*)d_in[15];
    const float* b3a = (const float*)d_in[16];
    float* out = (float*)d_out;

    __nv_bfloat16 *xch, *xcl, *h1h, *h1l, *h2h, *h2l;
    __nv_bfloat16 *w1oh, *w1ol, *w2oh, *w2ol, *w3oh, *w3ol;
    __nv_bfloat16 *w1ah, *w1al, *w2ah, *w2al, *w3ah, *w3al;
    float *lo, *la;
    float2 *sto, *sta;
    cudaGetSymbolAddress((void**)&xch, g_xc_hi);  cudaGetSymbolAddress((void**)&xcl, g_xc_lo);
    cudaGetSymbolAddress((void**)&h1h, g_h1_hi);  cudaGetSymbolAddress((void**)&h1l, g_h1_lo);
    cudaGetSymbolAddress((void**)&h2h, g_h2_hi);  cudaGetSymbolAddress((void**)&h2l, g_h2_lo);
    cudaGetSymbolAddress((void**)&w1oh, g_wt1o_hi); cudaGetSymbolAddress((void**)&w1ol, g_wt1o_lo);
    cudaGetSymbolAddress((void**)&w2oh, g_wt2o_hi); cudaGetSymbolAddress((void**)&w2ol, g_wt2o_lo);
    cudaGetSymbolAddress((void**)&w3oh, g_wt3o_hi); cudaGetSymbolAddress((void**)&w3ol, g_wt3o_lo);
    cudaGetSymbolAddress((void**)&w1ah, g_wt1a_hi); cudaGetSymbolAddress((void**)&w1al, g_wt1a_lo);
    cudaGetSymbolAddress((void**)&w2ah, g_wt2a_hi); cudaGetSymbolAddress((void**)&w2al, g_wt2a_lo);
    cudaGetSymbolAddress((void**)&w3ah, g_wt3a_hi); cudaGetSymbolAddress((void**)&w3al, g_wt3a_lo);
    cudaGetSymbolAddress((void**)&lo,  g_lo);
    cudaGetSymbolAddress((void**)&la,  g_la);
    cudaGetSymbolAddress((void**)&sto, g_st_o);
    cudaGetSymbolAddress((void**)&sta, g_st_a);

    cudaFuncSetAttribute(mma_gemm<0>, cudaFuncAttributeMaxDynamicSharedMemorySize, GEMM_SMEM);
    cudaFuncSetAttribute(mma_gemm<1>, cudaFuncAttributeMaxDynamicSharedMemorySize, GEMM_SMEM);

    const int MT = MM / 128;  // 100 M tiles max; blocks past g_Meff exit

    setup_kernel<<<1, BB>>>(num_descs);
    xsplit_kernel<<<MM, 256>>>(x);

    dim3 wb(32, 8);
    wsplit_kernel<<<dim3(HH/32,   DD/32), wb>>>(w1o, w1oh, w1ol, DD, HH);
    wsplit_kernel<<<dim3(HH/32,   HH/32), wb>>>(w2o, w2oh, w2ol, HH, HH);
    wsplit_kernel<<<dim3(OPAD/32, HH/32), wb>>>(w3o, w3oh, w3ol, HH, OO);
    wsplit_kernel<<<dim3(HH/32,   DD/32), wb>>>(w1a, w1ah, w1al, DD, HH);
    wsplit_kernel<<<dim3(HH/32,   HH/32), wb>>>(w2a, w2ah, w2al, HH, HH);
    wsplit_kernel<<<dim3(APAD/32, HH/32), wb>>>(w3a, w3ah, w3al, HH, AAd);

    // object branch
    mma_gemm<0><<<dim3(HH/128, MT), 256, GEMM_SMEM>>>(xch, xcl, w1oh, w1ol, b1o, nullptr, h1h, h1l, HH, DD);
    mma_gemm<0><<<dim3(HH/128, MT), 256, GEMM_SMEM>>>(h1h, h1l, w2oh, w2ol, b2o, nullptr, h2h, h2l, HH, HH);
    mma_gemm<1><<<dim3(OPAD/128, MT), 256, GEMM_SMEM>>>(h2h, h2l, w3oh, w3ol, b3o, lo, nullptr, nullptr, OO, HH);
    rowstats_kernel<<<MM, 128>>>(lo, sto, OO);

    // attribute branch (reuses h1/h2)
    mma_gemm<0><<<dim3(HH/128, MT), 256, GEMM_SMEM>>>(xch, xcl, w1ah, w1al, b1a, nullptr, h1h, h1l, HH, DD);
    mma_gemm<0><<<dim3(HH/128, MT), 256, GEMM_SMEM>>>(h1h, h1l, w2ah, w2al, b2a, nullptr, h2h, h2l, HH, HH);
    mma_gemm<1><<<dim3(APAD/128, MT), 256, GEMM_SMEM>>>(h2h, h2l, w3ah, w3al, b3a, la, nullptr, nullptr, AAd, HH);
    rowstats_kernel<<<MM, 128>>>(la, sta, AAd);

    score_kernel<<<(LL + 7) / 8, 256>>>(label_img, obj_labels, att_labels, num_descs);
    gather_kernel<<<LL, 256>>>(label_img, out);
}

// round 4
// speedup vs baseline: 2.8394x; 1.0050x over previous
#include <cuda_runtime.h>
#include <cuda_bf16.h>
#include <math.h>
#include <stdint.h>

// Problem constants
#define BB 128
#define NN 100
#define DD 2048
#define HH 1024
#define OO 1600
#define AAd 400
#define LL 2048
#define MM (BB*NN)   // 12800

#define OPAD 1664    // OO padded to 128
#define APAD 512     // AAd padded to 128

// ---------------- device scratch (no allocs allowed) ----------------
__device__ __nv_bfloat16 g_xc_hi[(size_t)MM * DD];
__device__ __nv_bfloat16 g_xc_lo[(size_t)MM * DD];
// per-branch hidden activations (split)
__device__ __nv_bfloat16 g_h1o_hi[(size_t)MM * HH];
__device__ __nv_bfloat16 g_h1o_lo[(size_t)MM * HH];
__device__ __nv_bfloat16 g_h1a_hi[(size_t)MM * HH];
__device__ __nv_bfloat16 g_h1a_lo[(size_t)MM * HH];
__device__ __nv_bfloat16 g_h2o_hi[(size_t)MM * HH];
__device__ __nv_bfloat16 g_h2o_lo[(size_t)MM * HH];
__device__ __nv_bfloat16 g_h2a_hi[(size_t)MM * HH];
__device__ __nv_bfloat16 g_h2a_lo[(size_t)MM * HH];
// transposed split weights  [Npad][K]
__device__ __nv_bfloat16 g_wt1o_hi[(size_t)HH * DD];
__device__ __nv_bfloat16 g_wt1o_lo[(size_t)HH * DD];
__device__ __nv_bfloat16 g_wt2o_hi[(size_t)HH * HH];
__device__ __nv_bfloat16 g_wt2o_lo[(size_t)HH * HH];
__device__ __nv_bfloat16 g_wt3o_hi[(size_t)OPAD * HH];
__device__ __nv_bfloat16 g_wt3o_lo[(size_t)OPAD * HH];
__device__ __nv_bfloat16 g_wt1a_hi[(size_t)HH * DD];
__device__ __nv_bfloat16 g_wt1a_lo[(size_t)HH * DD];
__device__ __nv_bfloat16 g_wt2a_hi[(size_t)HH * HH];
__device__ __nv_bfloat16 g_wt2a_lo[(size_t)HH * HH];
__device__ __nv_bfloat16 g_wt3a_hi[(size_t)APAD * HH];
__device__ __nv_bfloat16 g_wt3a_lo[(size_t)APAD * HH];
__device__ float g_lo[(size_t)MM * OO];
__device__ float g_la[(size_t)MM * AAd];
__device__ float2 g_st_o[MM];
__device__ float2 g_st_a[MM];
__device__ int   g_rowmap[MM];
__device__ int   g_rowstart[BB];
__device__ int   g_Meff;
__device__ int   g_desc[LL];

// ---------------- PTX helpers (baseline sm_80+ features only) ----------------
__device__ __forceinline__ uint32_t smem_u32_of(const void* p) {
    uint32_t a;
    asm("{ .reg .u64 t; cvta.to.shared.u64 t, %1; cvt.u32.u64 %0, t; }" : "=r"(a) : "l"(p));
    return a;
}
__device__ __forceinline__ void cp16(uint32_t dst, const void* src) {
    asm volatile("cp.async.cg.shared.global [%0], [%1], 16;" :: "r"(dst), "l"(src) : "memory");
}
__device__ __forceinline__ void cp_commit() {
    asm volatile("cp.async.commit_group;" ::: "memory");
}
template<int N>
__device__ __forceinline__ void cp_wait() {
    asm volatile("cp.async.wait_group %0;" :: "n"(N) : "memory");
}
__device__ __forceinline__ void ldsm4(uint32_t* r, uint32_t addr) {
    asm volatile("ldmatrix.sync.aligned.m8n8.x4.shared.b16 {%0,%1,%2,%3}, [%4];"
        : "=r"(r[0]), "=r"(r[1]), "=r"(r[2]), "=r"(r[3]) : "r"(addr));
}
__device__ __forceinline__ void mma16816(float* c, const uint32_t* a, const uint32_t* b) {
    asm volatile("mma.sync.aligned.m16n8k16.row.col.f32.bf16.bf16.f32 "
        "{%0,%1,%2,%3}, {%4,%5,%6,%7}, {%8,%9}, {%0,%1,%2,%3};"
        : "+f"(c[0]), "+f"(c[1]), "+f"(c[2]), "+f"(c[3])
        : "r"(a[0]), "r"(a[1]), "r"(a[2]), "r"(a[3]), "r"(b[0]), "r"(b[1]));
}

// ---------------- setup: live-row compaction ----------------
__global__ void setup_kernel(const int* __restrict__ num_descs) {
    __shared__ int cnt[BB];
    int b = threadIdx.x;
    int c = num_descs[b];
    if (c < 1) c = 1;
    cnt[b] = c;
    __syncthreads();
    if (b == 0) {
        int acc = 0;
        for (int i = 0; i < BB; i++) { g_rowstart[i] = acc; acc += cnt[i]; }
        g_Meff = acc;
    }
    __syncthreads();
    int start = g_rowstart[b];
    for (int i = 0; i < c; i++) g_rowmap[start + i] = b * NN + i;
}

// ---------------- x compaction + bf16 hi/lo split ----------------
__global__ void xsplit_kernel(const float* __restrict__ x) {
    int r = blockIdx.x;
    int Meff = g_Meff;
    int mceil = (Meff + 127) & ~127;
    if (r >= mceil) return;
    int src = g_rowmap[r < Meff ? r : (Meff - 1)];
    const float4* xp = (const float4*)(x + (size_t)src * DD);
    uint32_t* dh = (uint32_t*)(g_xc_hi + (size_t)r * DD);
    uint32_t* dl = (uint32_t*)(g_xc_lo + (size_t)r * DD);
    for (int i = threadIdx.x; i < DD / 4; i += 256) {
        float4 v = xp[i];
        __nv_bfloat16 h0 = __float2bfloat16(v.x);
        __nv_bfloat16 h1 = __float2bfloat16(v.y);
        __nv_bfloat16 h2 = __float2bfloat16(v.z);
        __nv_bfloat16 h3 = __float2bfloat16(v.w);
        __nv_bfloat16 l0 = __float2bfloat16(v.x - __bfloat162float(h0));
        __nv_bfloat16 l1 = __float2bfloat16(v.y - __bfloat162float(h1));
        __nv_bfloat16 l2 = __float2bfloat16(v.z - __bfloat162float(h2));
        __nv_bfloat16 l3 = __float2bfloat16(v.w - __bfloat162float(h3));
        __nv_bfloat162 ph0; ph0.x = h0; ph0.y = h1;
        __nv_bfloat162 ph1; ph1.x = h2; ph1.y = h3;
        __nv_bfloat162 pl0; pl0.x = l0; pl0.y = l1;
        __nv_bfloat162 pl1; pl1.x = l2; pl1.y = l3;
        dh[2*i]   = *(uint32_t*)&ph0;
        dh[2*i+1] = *(uint32_t*)&ph1;
        dl[2*i]   = *(uint32_t*)&pl0;
        dl[2*i+1] = *(uint32_t*)&pl1;
    }
}

// ---------------- weight transpose + split: W[K][N] -> T[Npad][K] hi/lo ----------------
__global__ void wsplit_kernel(const float* __restrict__ W,
                              __nv_bfloat16* __restrict__ Thi,
                              __nv_bfloat16* __restrict__ Tlo,
                              int K, int N) {
    __shared__ float t[32][33];
    int n0 = blockIdx.x * 32, k0 = blockIdx.y * 32;
    int tx = threadIdx.x, ty = threadIdx.y;
    for (int i = ty; i < 32; i += 8) {
        int n = n0 + tx;
        t[i][tx] = (n < N) ? W[(size_t)(k0 + i) * N + n] : 0.f;
    }
    __syncthreads();
    for (int i = ty; i < 32; i += 8) {
        int n = n0 + i;
        if (n < N) {
            float v = t[tx][i];
            __nv_bfloat16 h = __float2bfloat16(v);
            Thi[(size_t)n * K + k0 + tx] = h;
            Tlo[(size_t)n * K + k0 + tx] = __float2bfloat16(v - __bfloat162float(h));
        }
    }
}

// ---------------- HMMA split-bf16 GEMM ----------------
// Tile 128x128, K-chunk 64, cp.async 3-stage single-sync pipeline.
// smem per stage: Ahi|Alo|Bhi|Blo 16KB each = 64KB; 3 stages = 192KB.
#define STG_BYTES 65536
#define GEMM_SMEM (3 * STG_BYTES)

struct GArgs {
    const __nv_bfloat16 *Ahi0, *Alo0, *Bhi0, *Blo0;
    const __nv_bfloat16 *Ahi1, *Alo1, *Bhi1, *Blo1;
    const float *bias0, *bias1;
    float *Cf0, *Cf1;
    __nv_bfloat16 *Chi0, *Clo0, *Chi1, *Clo1;
    int N, K;
};

__device__ __forceinline__ void load_tile_async(const __nv_bfloat16* __restrict__ g,
                                                int rowStride, int row0, int k0,
                                                uint32_t sbase_tile, int tid) {
    #pragma unroll
    for (int it = 0; it < 4; it++) {
        int v = tid + it * 256;            // 0..1023
        int r = v >> 3, cv = v & 7;        // row, 16B chunk
        const void* src = g + (size_t)(row0 + r) * rowStride + k0 + cv * 8;
        uint32_t cb = (uint32_t)(cv * 16);
        uint32_t sw = (uint32_t)(r * 128) + (cb ^ (((uint32_t)r & 7u) << 4));
        cp16(sbase_tile + sw, src);
    }
}

__device__ __forceinline__ uint32_t swaddr(uint32_t base, int row, int cb) {
    return base + (uint32_t)(row * 128) + (((uint32_t)cb) ^ (((uint32_t)row & 7u) << 4));
}

// OUTMODE 0: relu + bf16 hi/lo outputs.  OUTMODE 1: fp32 outputs, no relu.
template<int OUTMODE>
__global__ __launch_bounds__(256, 1)
void mma_gemm(GArgs g)
{
    const int Meff = g_Meff;
    const int rowBase = blockIdx.y * 128;
    if (rowBase >= Meff) return;
    const int colBase = blockIdx.x * 128;
    const int tid = threadIdx.x;
    const int z = blockIdx.z;

    const __nv_bfloat16* Ahi = z ? g.Ahi1 : g.Ahi0;
    const __nv_bfloat16* Alo = z ? g.Alo1 : g.Alo0;
    const __nv_bfloat16* Bhi = z ? g.Bhi1 : g.Bhi0;
    const __nv_bfloat16* Blo = z ? g.Blo1 : g.Blo0;
    const float* bias        = z ? g.bias1 : g.bias0;
    float* Cf                = z ? g.Cf1 : g.Cf0;
    __nv_bfloat16* Chi       = z ? g.Chi1 : g.Chi0;
    __nv_bfloat16* Clo       = z ? g.Clo1 : g.Clo0;
    const int N = g.N, K = g.K;

    extern __shared__ char smem[];
    const uint32_t sbase = smem_u32_of(smem);

    const int warp = tid >> 5, lane = tid & 31;
    const int wm = (warp >> 2) * 64;
    const int wn = (warp & 3) * 32;

    float acc[4][4][4];
    #pragma unroll
    for (int i = 0; i < 4; i++)
        #pragma unroll
        for (int j = 0; j < 4; j++)
            #pragma unroll
            for (int c = 0; c < 4; c++) acc[i][j][c] = 0.f;

    const int nk = K >> 6;

    // prologue: stages 0 and 1
    #pragma unroll
    for (int p = 0; p < 2; p++) {
        uint32_t st = sbase + (uint32_t)p * STG_BYTES;
        load_tile_async(Ahi, K, rowBase, p * 64, st,          tid);
        load_tile_async(Alo, K, rowBase, p * 64, st + 16384,  tid);
        load_tile_async(Bhi, K, colBase, p * 64, st + 32768,  tid);
        load_tile_async(Blo, K, colBase, p * 64, st + 49152,  tid);
        cp_commit();
    }

    const int aRowL = wm + (lane & 15);
    const int aSel  = (lane >> 4);
    const int bRowL = wn + (lane & 7) + ((lane >> 4) << 3);
    const int bSel  = (lane >> 3) & 1;

    int scur = 0;   // stage of chunk i
    for (int i = 0; i < nk; i++) {
        cp_wait<1>();            // chunk i resident (chunk i+1 may still fly)
        __syncthreads();         // all warps done with stage (i-1)%3 == (i+2)%3

        // prefetch chunk i+2 into the just-freed slot, BEFORE compute
        int spre = scur + 2; if (spre >= 3) spre -= 3;
        if (i + 2 < nk) {
            const int k0 = (i + 2) << 6;
            uint32_t st = sbase + (uint32_t)spre * STG_BYTES;
            load_tile_async(Ahi, K, rowBase, k0, st,          tid);
            load_tile_async(Alo, K, rowBase, k0, st + 16384,  tid);
            load_tile_async(Bhi, K, colBase, k0, st + 32768,  tid);
            load_tile_async(Blo, K, colBase, k0, st + 49152,  tid);
        }
        cp_commit();             // uniform group count (empty group near tail)

        const uint32_t sA  = sbase + (uint32_t)scur * STG_BYTES;
        const uint32_t sAl = sA + 16384;
        const uint32_t sBh = sA + 32768;
        const uint32_t sBl = sA + 49152;

        #pragma unroll
        for (int kk = 0; kk < 4; kk++) {
            const int k0 = kk * 16;
            const int aCb = (k0 >> 3) * 16 + aSel * 16;
            const int bCb = (k0 >> 3) * 16 + bSel * 16;

            uint32_t af[16], bhf[8], blf[8];
            #pragma unroll
            for (int mi = 0; mi < 4; mi++)
                ldsm4(&af[mi * 4], swaddr(sA, aRowL + mi * 16, aCb));
            #pragma unroll
            for (int p = 0; p < 2; p++) {
                ldsm4(&bhf[p * 4], swaddr(sBh, bRowL + p * 16, bCb));
                ldsm4(&blf[p * 4], swaddr(sBl, bRowL + p * 16, bCb));
            }
            #pragma unroll
            for (int mi = 0; mi < 4; mi++)
                #pragma unroll
                for (int ni = 0; ni < 4; ni++) {
                    mma16816(acc[mi][ni], &af[mi * 4], &bhf[ni * 2]);
                    mma16816(acc[mi][ni], &af[mi * 4], &blf[ni * 2]);
                }
            #pragma unroll
            for (int mi = 0; mi < 4; mi++)
                ldsm4(&af[mi * 4], swaddr(sAl, aRowL + mi * 16, aCb));
            #pragma unroll
            for (int mi = 0; mi < 4; mi++)
                #pragma unroll
                for (int ni = 0; ni < 4; ni++)
                    mma16816(acc[mi][ni], &af[mi * 4], &bhf[ni * 2]);
        }

        scur += 1; if (scur >= 3) scur -= 3;
    }

    // epilogue from register accumulators
    #pragma unroll
    for (int mi = 0; mi < 4; mi++) {
        #pragma unroll
        for (int ni = 0; ni < 4; ni++) {
            const int col = colBase + wn + ni * 8 + (lane & 3) * 2;
            if (col < N) {
                const float2 bv = *(const float2*)(bias + col);
                #pragma unroll
                for (int h = 0; h < 2; h++) {
                    const int row = rowBase + wm + mi * 16 + (lane >> 2) + h * 8;
                    float v0 = acc[mi][ni][h * 2 + 0] + bv.x;
                    float v1 = acc[mi][ni][h * 2 + 1] + bv.y;
                    if (OUTMODE == 0) {
                        v0 = fmaxf(v0, 0.f);
                        v1 = fmaxf(v1, 0.f);
                        __nv_bfloat16 h0 = __float2bfloat16(v0);
                        __nv_bfloat16 h1 = __float2bfloat16(v1);
                        __nv_bfloat16 l0 = __float2bfloat16(v0 - __bfloat162float(h0));
                        __nv_bfloat16 l1 = __float2bfloat16(v1 - __bfloat162float(h1));
                        __nv_bfloat162 ph; ph.x = h0; ph.y = h1;
                        __nv_bfloat162 pl; pl.x = l0; pl.y = l1;
                        *(uint32_t*)(Chi + (size_t)row * N + col) = *(uint32_t*)&ph;
                        *(uint32_t*)(Clo + (size_t)row * N + col) = *(uint32_t*)&pl;
                    } else {
                        float2 v; v.x = v0; v.y = v1;
                        *(float2*)(Cf + (size_t)row * N + col) = v;
                    }
                }
            }
        }
    }
}

// ---------------- per-row softmax stats: (max, sum exp) ----------------
__global__ void rowstats_kernel(const float* __restrict__ logits,
                                float2* __restrict__ stats, int ncols)
{
    int r = blockIdx.x;
    if (r >= g_Meff) return;
    const float* p = logits + (size_t)r * ncols;
    const int tid = threadIdx.x;   // 128
    __shared__ float red[128];

    float mx = -3.402823466e38f;
    for (int j = tid; j < ncols; j += 128) mx = fmaxf(mx, p[j]);
    red[tid] = mx; __syncthreads();
    for (int s = 64; s; s >>= 1) {
        if (tid < s) red[tid] = fmaxf(red[tid], red[tid + s]);
        __syncthreads();
    }
    mx = red[0]; __syncthreads();

    float sum = 0.f;
    for (int j = tid; j < ncols; j += 128) sum += expf(p[j] - mx);
    red[tid] = sum; __syncthreads();
    for (int s = 64; s; s >>= 1) {
        if (tid < s) red[tid] += red[tid + s];
        __syncthreads();
    }
    if (tid == 0) stats[r] = make_float2(mx, red[0]);
}

// ---------------- score + argmax: one warp per label row ----------------
__global__ void score_kernel(const int* __restrict__ label_img,
                             const int* __restrict__ obj_labels,
                             const int* __restrict__ att_labels,
                             const int* __restrict__ num_descs)
{
    int l = blockIdx.x * 8 + (threadIdx.x >> 5);
    int lane = threadIdx.x & 31;
    if (l >= LL) return;
    int b  = label_img[l];
    int nd = num_descs[b];
    int oj = obj_labels[l];
    int aj = att_labels[l];
    int rs = g_rowstart[b];

    float best = -1.0f;
    int   bidx = 0;
    for (int n = lane; n < nd; n += 32) {
        int r = rs + n;
        float2 so = g_st_o[r];
        float2 sa = g_st_a[r];
        float po = expf(g_lo[(size_t)r * OO  + oj] - so.x) / so.y;
        float pa = expf(g_la[(size_t)r * AAd + aj] - sa.x) / sa.y;
        float s = po * pa;
        if (s > best) { best = s; bidx = n; }
    }
    #pragma unroll
    for (int off = 16; off; off >>= 1) {
        float ob = __shfl_down_sync(0xffffffffu, best, off);
        int   oi = __shfl_down_sync(0xffffffffu, bidx, off);
        if (ob > best || (ob == best && oi < bidx)) { best = ob; bidx = oi; }
    }
    if (lane == 0) g_desc[l] = bidx;
}

// ---------------- final gather: softmax of the selected row ----------------
__global__ void gather_kernel(const int* __restrict__ label_img,
                              float* __restrict__ out)
{
    int l = blockIdx.x;
    int b = label_img[l];
    int r = g_rowstart[b] + g_desc[l];

    float2 so = g_st_o[r];
    float inv_o = 1.0f / so.y;
    const float* lo = g_lo + (size_t)r * OO;
    float* oo = out + (size_t)l * OO;
    for (int j = threadIdx.x; j < OO; j += blockDim.x)
        oo[j] = expf(lo[j] - so.x) * inv_o;

    float2 sa = g_st_a[r];
    float inv_a = 1.0f / sa.y;
    const float* la = g_la + (size_t)r * AAd;
    float* oa = out + (size_t)LL * OO + (size_t)l * AAd;
    for (int j = threadIdx.x; j < AAd; j += blockDim.x)
        oa[j] = expf(la[j] - sa.x) * inv_a;
}

// ---------------- launch ----------------
extern "C" void kernel_launch(void* const* d_in, const int* in_sizes, int n_in,
                              void* d_out, int out_size)
{
    const float* x          = (const float*)d_in[0];
    const int*   num_descs  = (const int*)  d_in[1];
    const int*   label_img  = (const int*)  d_in[2];
    const int*   obj_labels = (const int*)  d_in[3];
    const int*   att_labels = (const int*)  d_in[4];
    const float* w1o = (const float*)d_in[5];
    const float* b1o = (const float*)d_in[6];
    const float* w2o = (const float*)d_in[7];
    const float* b2o = (const float*)d_in[8];
    const float* w3o = (const float*)d_in[9];
    const float* b3o = (const float*)d_in[10];
    const float* w1a = (const float*)d_in[11];
    const float* b1a = (const float*)d_in[12];
    const float* w2a = (const float*)d_in[13];
    const float* b2a = (const float*)d_in[14];
    const float* w3a = (const float*)d_in[15];
    const float* b3a = (const float*)d_in[16];
    float* out = (float*)d_out;

    __nv_bfloat16 *xch, *xcl;
    __nv_bfloat16 *h1oh, *h1ol, *h1ah, *h1al, *h2oh, *h2ol, *h2ah, *h2al;
    __nv_bfloat16 *w1oh, *w1ol, *w2oh, *w2ol, *w3oh, *w3ol;
    __nv_bfloat16 *w1ah, *w1al, *w2ah, *w2al, *w3ah, *w3al;
    float *lo, *la;
    float2 *sto, *sta;
    cudaGetSymbolAddress((void**)&xch, g_xc_hi);   cudaGetSymbolAddress((void**)&xcl, g_xc_lo);
    cudaGetSymbolAddress((void**)&h1oh, g_h1o_hi); cudaGetSymbolAddress((void**)&h1ol, g_h1o_lo);
    cudaGetSymbolAddress((void**)&h1ah, g_h1a_hi); cudaGetSymbolAddress((void**)&h1al, g_h1a_lo);
    cudaGetSymbolAddress((void**)&h2oh, g_h2o_hi); cudaGetSymbolAddress((void**)&h2ol, g_h2o_lo);
    cudaGetSymbolAddress((void**)&h2ah, g_h2a_hi); cudaGetSymbolAddress((void**)&h2al, g_h2a_lo);
    cudaGetSymbolAddress((void**)&w1oh, g_wt1o_hi); cudaGetSymbolAddress((void**)&w1ol, g_wt1o_lo);
    cudaGetSymbolAddress((void**)&w2oh, g_wt2o_hi); cudaGetSymbolAddress((void**)&w2ol, g_wt2o_lo);
    cudaGetSymbolAddress((void**)&w3oh, g_wt3o_hi); cudaGetSymbolAddress((void**)&w3ol, g_wt3o_lo);
    cudaGetSymbolAddress((void**)&w1ah, g_wt1a_hi); cudaGetSymbolAddress((void**)&w1al, g_wt1a_lo);
    cudaGetSymbolAddress((void**)&w2ah, g_wt2a_hi); cudaGetSymbolAddress((void**)&w2al, g_wt2a_lo);
    cudaGetSymbolAddress((void**)&w3ah, g_wt3a_hi); cudaGetSymbolAddress((void**)&w3al, g_wt3a_lo);
    cudaGetSymbolAddress((void**)&lo,  g_lo);
    cudaGetSymbolAddress((void**)&la,  g_la);
    cudaGetSymbolAddress((void**)&sto, g_st_o);
    cudaGetSymbolAddress((void**)&sta, g_st_a);

    cudaFuncSetAttribute(mma_gemm<0>, cudaFuncAttributeMaxDynamicSharedMemorySize, GEMM_SMEM);
    cudaFuncSetAttribute(mma_gemm<1>, cudaFuncAttributeMaxDynamicSharedMemorySize, GEMM_SMEM);

    const int MT = MM / 128;  // 100 M tiles max; blocks past g_Meff exit
    dim3 wb(32, 8);

    // Launch order puts the merged layer-1 GEMM at launch #6 (ncu -s 5 -c 1).
    setup_kernel<<<1, BB>>>(num_descs);                              // 1
    xsplit_kernel<<<MM, 256>>>(x);                                   // 2
    wsplit_kernel<<<dim3(HH/32, DD/32), wb>>>(w1o, w1oh, w1ol, DD, HH); // 3
    wsplit_kernel<<<dim3(HH/32, DD/32), wb>>>(w1a, w1ah, w1al, DD, HH); // 4
    wsplit_kernel<<<dim3(HH/32, HH/32), wb>>>(w2o, w2oh, w2ol, HH, HH); // 5

    GArgs a1 = { xch, xcl, w1oh, w1ol,
                 xch, xcl, w1ah, w1al,
                 b1o, b1a, nullptr, nullptr,
                 h1oh, h1ol, h1ah, h1al, HH, DD };
    mma_gemm<0><<<dim3(HH/128, MT, 2), 256, GEMM_SMEM>>>(a1);        // 6 <- profiled

    wsplit_kernel<<<dim3(HH/32, HH/32), wb>>>(w2a, w2ah, w2al, HH, HH);
    wsplit_kernel<<<dim3(OPAD/32, HH/32), wb>>>(w3o, w3oh, w3ol, HH, OO);
    wsplit_kernel<<<dim3(APAD/32, HH/32), wb>>>(w3a, w3ah, w3al, HH, AAd);

    GArgs a2 = { h1oh, h1ol, w2oh, w2ol,
                 h1ah, h1al, w2ah, w2al,
                 b2o, b2a, nullptr, nullptr,
                 h2oh, h2ol, h2ah, h2al, HH, HH };
    mma_gemm<0><<<dim3(HH/128, MT, 2), 256, GEMM_SMEM>>>(a2);

    GArgs a3o = { h2oh, h2ol, w3oh, w3ol,
                  h2oh, h2ol, w3oh, w3ol,
                  b3o, b3o, lo, lo,
                  nullptr, nullptr, nullptr, nullptr, OO, HH };
    mma_gemm<1><<<dim3(OPAD/128, MT, 1), 256, GEMM_SMEM>>>(a3o);

    GArgs a3a = { h2ah, h2al, w3ah, w3al,
                  h2ah, h2al, w3ah, w3al,
                  b3a, b3a, la, la,
                  nullptr, nullptr, nullptr, nullptr, AAd, HH };
    mma_gemm<1><<<dim3(APAD/128, MT, 1), 256, GEMM_SMEM>>>(a3a);

    rowstats_kernel<<<MM, 128>>>(lo, sto, OO);
    rowstats_kernel<<<MM, 128>>>(la, sta, AAd);
    score_kernel<<<(LL + 7) / 8, 256>>>(label_img, obj_labels, att_labels, num_descs);
    gather_kernel<<<LL, 256>>>(label_img, out);
}